// round 5
// baseline (speedup 1.0000x reference)
#include <cuda_runtime.h>
#include <cstdint>

#define N_TYPES 20
#define LMAX    13
#define LPAD    16
#define DV      64
#define BATCH   16
#define TPB     192   // = DV*3, one thread per (v,d) output lane
#define MT      4     // m-tile

__device__ const int d_res_len[N_TYPES] = {3,4,5,5,6,6,6,7,7,7,7,7,8,8,8,9,10,10,11,13};
__device__ int   g_starts[4096];
__device__ float g_Wp_atm[N_TYPES * LMAX * DV * LPAD];  // [t][m][v][lpad], zero for l>=13
__device__ float g_Wp_amn[N_TYPES * DV * LPAD];         // [t][v][lpad],    zero for l>=13

// One-block exclusive prefix scan of residue lengths -> g_starts
__global__ void posmix_scan_kernel(const int* __restrict__ seq, int n_res) {
    __shared__ int ps[1024];
    int t = threadIdx.x;
    int i0 = 2*t, i1 = 2*t + 1;
    int l0 = (i0 < n_res) ? d_res_len[seq[i0]] : 0;
    int l1 = (i1 < n_res) ? d_res_len[seq[i1]] : 0;
    ps[t] = l0 + l1;
    __syncthreads();
    for (int off = 1; off < 1024; off <<= 1) {
        int v = ps[t];
        int a = (t >= off) ? ps[t - off] : 0;
        __syncthreads();
        ps[t] = v + a;
        __syncthreads();
    }
    int excl = (t == 0) ? 0 : ps[t - 1];
    if (i0 < n_res) g_starts[i0] = excl;
    if (i1 < n_res) g_starts[i1] = excl + l0;
}

// Repack weights with l padded 13 -> 16 (zero fill) for vector loads.
__global__ void posmix_pack_kernel(const float* __restrict__ W_amn,
                                   const float* __restrict__ W_atm) {
    int i = blockIdx.x * blockDim.x + threadIdx.x;
    const int total_atm = N_TYPES * LMAX * DV * LPAD;
    const int total_amn = N_TYPES * DV * LPAD;
    if (i < total_atm) {
        int l = i & (LPAD - 1);
        int r = i >> 4;                       // (t*13+m)*64+v
        g_Wp_atm[i] = (l < LMAX) ? W_atm[r * LMAX + l] : 0.f;
    } else if (i < total_atm + total_amn) {
        int j = i - total_atm;
        int l = j & (LPAD - 1);
        int r = j >> 4;                       // t*64+v
        g_Wp_amn[j] = (l < LMAX) ? W_amn[r * LMAX + l] : 0.f;
    }
}

__device__ __forceinline__ void fma16(float* acc, float wv,
                                      float4 q0, float4 q1, float4 q2, float4 q3)
{
    acc[0]  = fmaf(wv, q0.x, acc[0]);
    acc[1]  = fmaf(wv, q0.y, acc[1]);
    acc[2]  = fmaf(wv, q0.z, acc[2]);
    acc[3]  = fmaf(wv, q0.w, acc[3]);
    acc[4]  = fmaf(wv, q1.x, acc[4]);
    acc[5]  = fmaf(wv, q1.y, acc[5]);
    acc[6]  = fmaf(wv, q1.z, acc[6]);
    acc[7]  = fmaf(wv, q1.w, acc[7]);
    acc[8]  = fmaf(wv, q2.x, acc[8]);
    acc[9]  = fmaf(wv, q2.y, acc[9]);
    acc[10] = fmaf(wv, q2.z, acc[10]);
    acc[11] = fmaf(wv, q2.w, acc[11]);
    acc[12] = fmaf(wv, q3.x, acc[12]);
    acc[13] = fmaf(wv, q3.y, acc[13]);
    acc[14] = fmaf(wv, q3.z, acc[14]);
    acc[15] = fmaf(wv, q3.w, acc[15]);
}

__device__ __forceinline__ float f4elem(float4 w, int s) {
    return (s == 0) ? w.x : (s == 1) ? w.y : (s == 2) ? w.z : w.w;
}

__global__ __launch_bounds__(TPB, 3)
void posmix_kernel(const float* __restrict__ pos_atm,
                   const float* __restrict__ pos_amn,
                   const int*   __restrict__ seq,
                   float* __restrict__ out,
                   int atoms, int n_res, int amn_base)
{
    // diff_s[(l*3+d)*20 + b], l zero-padded to LPAD. Stride 20 floats keeps
    // float4 alignment and avoids bank aliasing.
    __shared__ float diff_s[LPAD * 3 * 20];

    const int n   = blockIdx.x;
    const int tp  = seq[n];
    const int L   = d_res_len[tp];
    const int st  = g_starts[n];
    const int tid = threadIdx.x;
    const int v   = tid / 3;
    const int d   = tid - 3 * v;

    // Single-pass fill: data for l < L, zeros for L <= l < LPAD.
    for (int i = tid; i < LPAD * 3 * BATCH; i += TPB) {
        int b  = i & (BATCH - 1);
        int q  = i >> 4;
        int dd = q % 3;
        int l  = q / 3;
        float val = 0.f;
        if (l < L) {
            val = pos_atm[((size_t)b * atoms + st + l) * 3 + dd]
                - pos_amn[((size_t)b * n_res + n) * 3 + dd];
        }
        diff_s[(l * 3 + dd) * 20 + b] = val;
    }
    __syncthreads();

    const int NC   = (L + 3) >> 2;          // l-chunks of 4
    const int bstr = atoms * (DV * 3);      // batch stride in out (atm region)
    const float* Wbase = g_Wp_atm + ((size_t)(tp * LMAX) * DV + v) * LPAD;

    // ---- x_v_atm rows, m-tiled by MT ----
    for (int m0 = 0; m0 < L; m0 += MT) {
        int mo0 = ((m0 + 0 < L) ? (m0 + 0) : (L - 1)) * (DV * LPAD);
        int mo1 = ((m0 + 1 < L) ? (m0 + 1) : (L - 1)) * (DV * LPAD);
        int mo2 = ((m0 + 2 < L) ? (m0 + 2) : (L - 1)) * (DV * LPAD);
        int mo3 = ((m0 + 3 < L) ? (m0 + 3) : (L - 1)) * (DV * LPAD);

        float acc0[BATCH], acc1[BATCH], acc2[BATCH], acc3[BATCH];
        #pragma unroll
        for (int b = 0; b < BATCH; ++b) {
            acc0[b] = 0.f; acc1[b] = 0.f; acc2[b] = 0.f; acc3[b] = 0.f;
        }

        for (int c = 0; c < NC; ++c) {
            float4 w0 = *reinterpret_cast<const float4*>(Wbase + mo0 + c * 4);
            float4 w1 = *reinterpret_cast<const float4*>(Wbase + mo1 + c * 4);
            float4 w2 = *reinterpret_cast<const float4*>(Wbase + mo2 + c * 4);
            float4 w3 = *reinterpret_cast<const float4*>(Wbase + mo3 + c * 4);
            #pragma unroll
            for (int s = 0; s < 4; ++s) {
                int l = c * 4 + s;
                const float4* dp = reinterpret_cast<const float4*>(diff_s + (l * 3 + d) * 20);
                float4 q0 = dp[0], q1 = dp[1], q2 = dp[2], q3 = dp[3];
                fma16(acc0, f4elem(w0, s), q0, q1, q2, q3);
                fma16(acc1, f4elem(w1, s), q0, q1, q2, q3);
                fma16(acc2, f4elem(w2, s), q0, q1, q2, q3);
                fma16(acc3, f4elem(w3, s), q0, q1, q2, q3);
            }
        }

        int ob = (st + m0) * (DV * 3) + tid;
        if (m0 + 0 < L) {
            #pragma unroll
            for (int b = 0; b < BATCH; ++b) out[ob + 0 * (DV * 3) + b * bstr] = acc0[b];
        }
        if (m0 + 1 < L) {
            #pragma unroll
            for (int b = 0; b < BATCH; ++b) out[ob + 1 * (DV * 3) + b * bstr] = acc1[b];
        }
        if (m0 + 2 < L) {
            #pragma unroll
            for (int b = 0; b < BATCH; ++b) out[ob + 2 * (DV * 3) + b * bstr] = acc2[b];
        }
        if (m0 + 3 < L) {
            #pragma unroll
            for (int b = 0; b < BATCH; ++b) out[ob + 3 * (DV * 3) + b * bstr] = acc3[b];
        }
    }

    // ---- x_v_amn row ----
    {
        const float* Wrow = g_Wp_amn + (tp * DV + v) * LPAD;
        float acc[BATCH];
        #pragma unroll
        for (int b = 0; b < BATCH; ++b) acc[b] = 0.f;

        for (int c = 0; c < NC; ++c) {
            float4 w = *reinterpret_cast<const float4*>(Wrow + c * 4);
            #pragma unroll
            for (int s = 0; s < 4; ++s) {
                int l = c * 4 + s;
                const float4* dp = reinterpret_cast<const float4*>(diff_s + (l * 3 + d) * 20);
                float4 q0 = dp[0], q1 = dp[1], q2 = dp[2], q3 = dp[3];
                fma16(acc, f4elem(w, s), q0, q1, q2, q3);
            }
        }

        int ob   = amn_base + n * (DV * 3) + tid;
        int bamn = n_res * (DV * 3);
        #pragma unroll
        for (int b = 0; b < BATCH; ++b) out[ob + b * bamn] = acc[b];
    }
}

extern "C" void kernel_launch(void* const* d_in, const int* in_sizes, int n_in,
                              void* d_out, int out_size)
{
    const float* pos_atm = (const float*)d_in[0];
    const float* pos_amn = (const float*)d_in[1];
    const float* W_amn   = (const float*)d_in[2];
    const float* W_atm   = (const float*)d_in[3];
    const int*   seq     = (const int*)d_in[4];

    const int n_res = in_sizes[4];                    // 2048
    const int atoms = in_sizes[0] / (BATCH * 3);      // 15036
    const int amn_base = BATCH * atoms * (DV * 3);    // 46,190,592 < 2^31

    float* out = (float*)d_out;

    const int pack_total = N_TYPES * LMAX * DV * LPAD + N_TYPES * DV * LPAD;
    posmix_scan_kernel<<<1, 1024>>>(seq, n_res);
    posmix_pack_kernel<<<(pack_total + 255) / 256, 256>>>(W_amn, W_atm);
    posmix_kernel<<<n_res, TPB>>>(pos_atm, pos_amn, seq, out,
                                  atoms, n_res, amn_base);
}

// round 10
// speedup vs baseline: 1.2346x; 1.2346x over previous
#include <cuda_runtime.h>
#include <cstdint>

#define N_TYPES 20
#define LMAX    13
#define DV      64
#define BATCH   16
#define TPB     192   // = DV*3, one thread per (v,d) output lane
#define MT      4     // m-tile

__device__ const int d_res_len[N_TYPES] = {3,4,5,5,6,6,6,7,7,7,7,7,8,8,8,9,10,10,11,13};
__device__ int g_starts[4096];

// 256-thread shfl-based exclusive scan of residue lengths (n_res <= 4096)
__global__ void posmix_scan_kernel(const int* __restrict__ seq, int n_res) {
    __shared__ int warp_sums[8];
    const int t = threadIdx.x;            // 0..255
    const int lane = t & 31, wid = t >> 5;
    const int per = (n_res + 255) / 256;  // elems per thread (8 for 2048)

    int lens[16];
    int s = 0;
    for (int j = 0; j < per; ++j) {
        int i = t * per + j;
        int l = (i < n_res) ? d_res_len[seq[i]] : 0;
        lens[j] = l;
        s += l;
    }
    // inclusive warp scan of per-thread sums
    int ps = s;
    #pragma unroll
    for (int off = 1; off < 32; off <<= 1) {
        int o = __shfl_up_sync(0xffffffffu, ps, off);
        if (lane >= off) ps += o;
    }
    if (lane == 31) warp_sums[wid] = ps;
    __syncthreads();
    if (wid == 0) {
        int ws = (lane < 8) ? warp_sums[lane] : 0;
        #pragma unroll
        for (int off = 1; off < 8; off <<= 1) {
            int o = __shfl_up_sync(0xffffffffu, ws, off);
            if (lane >= off) ws += o;
        }
        if (lane < 8) warp_sums[lane] = ws;
    }
    __syncthreads();
    int base = ps - s + ((wid > 0) ? warp_sums[wid - 1] : 0);  // exclusive prefix for this thread
    for (int j = 0; j < per; ++j) {
        int i = t * per + j;
        if (i < n_res) g_starts[i] = base;
        base += lens[j];
    }
}

__device__ __forceinline__ void fma16(float* acc, float wv,
                                      float4 q0, float4 q1, float4 q2, float4 q3)
{
    acc[0]  = fmaf(wv, q0.x, acc[0]);
    acc[1]  = fmaf(wv, q0.y, acc[1]);
    acc[2]  = fmaf(wv, q0.z, acc[2]);
    acc[3]  = fmaf(wv, q0.w, acc[3]);
    acc[4]  = fmaf(wv, q1.x, acc[4]);
    acc[5]  = fmaf(wv, q1.y, acc[5]);
    acc[6]  = fmaf(wv, q1.z, acc[6]);
    acc[7]  = fmaf(wv, q1.w, acc[7]);
    acc[8]  = fmaf(wv, q2.x, acc[8]);
    acc[9]  = fmaf(wv, q2.y, acc[9]);
    acc[10] = fmaf(wv, q2.z, acc[10]);
    acc[11] = fmaf(wv, q2.w, acc[11]);
    acc[12] = fmaf(wv, q3.x, acc[12]);
    acc[13] = fmaf(wv, q3.y, acc[13]);
    acc[14] = fmaf(wv, q3.z, acc[14]);
    acc[15] = fmaf(wv, q3.w, acc[15]);
}

__global__ __launch_bounds__(TPB, 3)
void posmix_kernel(const float* __restrict__ pos_atm,
                   const float* __restrict__ pos_amn,
                   const float* __restrict__ W_amn,
                   const float* __restrict__ W_atm,
                   const int*   __restrict__ seq,
                   float* __restrict__ out,
                   int atoms, int n_res, int amn_base)
{
    // diff_s[(l*3+d)*20 + b] : stride 20 floats keeps float4 alignment and
    // avoids the d0/d2 bank alias of stride 16.
    __shared__ float diff_s[LMAX * 3 * 20];

    const int n   = blockIdx.x;
    const int tp  = seq[n];
    const int L   = d_res_len[tp];
    const int st  = g_starts[n];
    const int tid = threadIdx.x;
    const int v   = tid / 3;
    const int d   = tid - 3 * v;

    // Cooperative diff fill: i -> (l, dd, b) with cheap const divisors
    const int tot = L * 48;                // L*3*16
    for (int i = tid; i < tot; i += TPB) {
        int l  = i / 48;
        int r  = i - l * 48;
        int dd = r >> 4;
        int b  = r & 15;
        float pa = pos_atm[(b * atoms + st + l) * 3 + dd];
        float pm = pos_amn[(b * n_res + n) * 3 + dd];
        diff_s[(l * 3 + dd) * 20 + b] = pa - pm;
    }
    __syncthreads();

    // W_atm layout: ((t*13+m)*64+v)*13 + l
    const int  wbase = tp * (LMAX * DV * LMAX) + v * LMAX;   // add m*(DV*LMAX)
    const int  bstr  = atoms * (DV * 3);

    for (int m0 = 0; m0 < L; m0 += MT) {
        const int mc0 = (m0 + 0 < L) ? (m0 + 0) : (L - 1);
        const int mc1 = (m0 + 1 < L) ? (m0 + 1) : (L - 1);
        const int mc2 = (m0 + 2 < L) ? (m0 + 2) : (L - 1);
        const int mc3 = (m0 + 3 < L) ? (m0 + 3) : (L - 1);
        const float* r0 = W_atm + wbase + mc0 * (DV * LMAX);
        const float* r1 = W_atm + wbase + mc1 * (DV * LMAX);
        const float* r2 = W_atm + wbase + mc2 * (DV * LMAX);
        const float* r3 = W_atm + wbase + mc3 * (DV * LMAX);

        float acc0[BATCH], acc1[BATCH], acc2[BATCH], acc3[BATCH];
        #pragma unroll
        for (int b = 0; b < BATCH; ++b) {
            acc0[b] = 0.f; acc1[b] = 0.f; acc2[b] = 0.f; acc3[b] = 0.f;
        }

        for (int l = 0; l < L; ++l) {
            const float4* dp = reinterpret_cast<const float4*>(diff_s + (l * 3 + d) * 20);
            float4 q0 = dp[0], q1 = dp[1], q2 = dp[2], q3 = dp[3];
            float w0 = __ldg(r0 + l);
            float w1 = __ldg(r1 + l);
            float w2 = __ldg(r2 + l);
            float w3 = __ldg(r3 + l);
            fma16(acc0, w0, q0, q1, q2, q3);
            fma16(acc1, w1, q0, q1, q2, q3);
            fma16(acc2, w2, q0, q1, q2, q3);
            fma16(acc3, w3, q0, q1, q2, q3);
        }

        const int ob = (st + m0) * (DV * 3) + tid;
        if (m0 + 0 < L) {
            #pragma unroll
            for (int b = 0; b < BATCH; ++b) out[ob + 0 * (DV * 3) + b * bstr] = acc0[b];
        }
        if (m0 + 1 < L) {
            #pragma unroll
            for (int b = 0; b < BATCH; ++b) out[ob + 1 * (DV * 3) + b * bstr] = acc1[b];
        }
        if (m0 + 2 < L) {
            #pragma unroll
            for (int b = 0; b < BATCH; ++b) out[ob + 2 * (DV * 3) + b * bstr] = acc2[b];
        }
        if (m0 + 3 < L) {
            #pragma unroll
            for (int b = 0; b < BATCH; ++b) out[ob + 3 * (DV * 3) + b * bstr] = acc3[b];
        }
    }

    // ---- x_v_amn tail ----
    {
        const float* wr = W_amn + (tp * DV + v) * LMAX;
        float acc[BATCH];
        #pragma unroll
        for (int b = 0; b < BATCH; ++b) acc[b] = 0.f;

        for (int l = 0; l < L; ++l) {
            const float4* dp = reinterpret_cast<const float4*>(diff_s + (l * 3 + d) * 20);
            float4 q0 = dp[0], q1 = dp[1], q2 = dp[2], q3 = dp[3];
            fma16(acc, __ldg(wr + l), q0, q1, q2, q3);
        }

        const int ob   = amn_base + n * (DV * 3) + tid;
        const int bamn = n_res * (DV * 3);
        #pragma unroll
        for (int b = 0; b < BATCH; ++b) out[ob + b * bamn] = acc[b];
    }
}

extern "C" void kernel_launch(void* const* d_in, const int* in_sizes, int n_in,
                              void* d_out, int out_size)
{
    const float* pos_atm = (const float*)d_in[0];
    const float* pos_amn = (const float*)d_in[1];
    const float* W_amn   = (const float*)d_in[2];
    const float* W_atm   = (const float*)d_in[3];
    const int*   seq     = (const int*)d_in[4];

    const int n_res = in_sizes[4];                    // 2048
    const int atoms = in_sizes[0] / (BATCH * 3);      // 15036
    const int amn_base = BATCH * atoms * (DV * 3);    // < 2^31

    float* out = (float*)d_out;

    posmix_scan_kernel<<<1, 256>>>(seq, n_res);
    posmix_kernel<<<n_res, TPB>>>(pos_atm, pos_amn, W_amn, W_atm, seq, out,
                                  atoms, n_res, amn_base);
}

// round 14
// speedup vs baseline: 1.2719x; 1.0302x over previous
#include <cuda_runtime.h>
#include <cstdint>

#define N_TYPES 20
#define LMAX    13
#define DV      64
#define BATCH   16
#define BH      8     // batches per block (batch split in half)
#define TPB     192   // = DV*3, one thread per (v,d) output lane
#define MT      4     // m-tile

__device__ const int d_res_len[N_TYPES] = {3,4,5,5,6,6,6,7,7,7,7,7,8,8,8,9,10,10,11,13};
__device__ int g_starts[4096];

// 256-thread shfl-based exclusive scan of residue lengths (n_res <= 4096)
__global__ void posmix_scan_kernel(const int* __restrict__ seq, int n_res) {
    __shared__ int warp_sums[8];
    const int t = threadIdx.x;            // 0..255
    const int lane = t & 31, wid = t >> 5;
    const int per = (n_res + 255) / 256;  // elems per thread (8 for 2048)

    int lens[16];
    int s = 0;
    for (int j = 0; j < per; ++j) {
        int i = t * per + j;
        int l = (i < n_res) ? d_res_len[seq[i]] : 0;
        lens[j] = l;
        s += l;
    }
    int ps = s;
    #pragma unroll
    for (int off = 1; off < 32; off <<= 1) {
        int o = __shfl_up_sync(0xffffffffu, ps, off);
        if (lane >= off) ps += o;
    }
    if (lane == 31) warp_sums[wid] = ps;
    __syncthreads();
    if (wid == 0) {
        int ws = (lane < 8) ? warp_sums[lane] : 0;
        #pragma unroll
        for (int off = 1; off < 8; off <<= 1) {
            int o = __shfl_up_sync(0xffffffffu, ws, off);
            if (lane >= off) ws += o;
        }
        if (lane < 8) warp_sums[lane] = ws;
    }
    __syncthreads();
    int base = ps - s + ((wid > 0) ? warp_sums[wid - 1] : 0);
    for (int j = 0; j < per; ++j) {
        int i = t * per + j;
        if (i < n_res) g_starts[i] = base;
        base += lens[j];
    }
}

__device__ __forceinline__ void fma8(float* acc, float wv, float4 q0, float4 q1)
{
    acc[0] = fmaf(wv, q0.x, acc[0]);
    acc[1] = fmaf(wv, q0.y, acc[1]);
    acc[2] = fmaf(wv, q0.z, acc[2]);
    acc[3] = fmaf(wv, q0.w, acc[3]);
    acc[4] = fmaf(wv, q1.x, acc[4]);
    acc[5] = fmaf(wv, q1.y, acc[5]);
    acc[6] = fmaf(wv, q1.z, acc[6]);
    acc[7] = fmaf(wv, q1.w, acc[7]);
}

__global__ __launch_bounds__(TPB, 4)
void posmix_kernel(const float* __restrict__ pos_atm,
                   const float* __restrict__ pos_amn,
                   const float* __restrict__ W_amn,
                   const float* __restrict__ W_atm,
                   const int*   __restrict__ seq,
                   float* __restrict__ out,
                   int atoms, int n_res, int amn_base)
{
    // diff_s[(l*3+d)*8 + b] for this block's 8 batches. 32B-aligned rows;
    // d-rows within a warp hit disjoint 8-bank groups -> conflict-free.
    __shared__ float diff_s[LMAX * 3 * BH];

    const int n   = blockIdx.x;
    const int b0  = blockIdx.y * BH;      // batch offset of this block
    const int tp  = seq[n];
    const int L   = d_res_len[tp];
    const int st  = g_starts[n];
    const int tid = threadIdx.x;
    const int v   = tid / 3;
    const int d   = tid - 3 * v;

    // Cooperative diff fill
    const int tot = L * 3 * BH;           // up to 312
    for (int i = tid; i < tot; i += TPB) {
        int l  = i / 24;
        int r  = i - l * 24;
        int dd = r >> 3;
        int b  = r & 7;
        float pa = pos_atm[((b0 + b) * atoms + st + l) * 3 + dd];
        float pm = pos_amn[((b0 + b) * n_res + n) * 3 + dd];
        diff_s[(l * 3 + dd) * BH + b] = pa - pm;
    }
    __syncthreads();

    // W_atm layout: ((t*13+m)*64+v)*13 + l
    const int wbase = tp * (LMAX * DV * LMAX) + v * LMAX;
    const int bstr  = atoms * (DV * 3);

    for (int m0 = 0; m0 < L; m0 += MT) {
        const int mc0 = (m0 + 0 < L) ? (m0 + 0) : (L - 1);
        const int mc1 = (m0 + 1 < L) ? (m0 + 1) : (L - 1);
        const int mc2 = (m0 + 2 < L) ? (m0 + 2) : (L - 1);
        const int mc3 = (m0 + 3 < L) ? (m0 + 3) : (L - 1);
        const float* r0 = W_atm + wbase + mc0 * (DV * LMAX);
        const float* r1 = W_atm + wbase + mc1 * (DV * LMAX);
        const float* r2 = W_atm + wbase + mc2 * (DV * LMAX);
        const float* r3 = W_atm + wbase + mc3 * (DV * LMAX);

        float acc0[BH], acc1[BH], acc2[BH], acc3[BH];
        #pragma unroll
        for (int b = 0; b < BH; ++b) {
            acc0[b] = 0.f; acc1[b] = 0.f; acc2[b] = 0.f; acc3[b] = 0.f;
        }

        for (int l = 0; l < L; ++l) {
            const float4* dp = reinterpret_cast<const float4*>(diff_s + (l * 3 + d) * BH);
            float4 q0 = dp[0], q1 = dp[1];
            float w0 = __ldg(r0 + l);
            float w1 = __ldg(r1 + l);
            float w2 = __ldg(r2 + l);
            float w3 = __ldg(r3 + l);
            fma8(acc0, w0, q0, q1);
            fma8(acc1, w1, q0, q1);
            fma8(acc2, w2, q0, q1);
            fma8(acc3, w3, q0, q1);
        }

        const int ob = (st + m0) * (DV * 3) + b0 * bstr + tid;
        if (m0 + 0 < L) {
            #pragma unroll
            for (int b = 0; b < BH; ++b) out[ob + 0 * (DV * 3) + b * bstr] = acc0[b];
        }
        if (m0 + 1 < L) {
            #pragma unroll
            for (int b = 0; b < BH; ++b) out[ob + 1 * (DV * 3) + b * bstr] = acc1[b];
        }
        if (m0 + 2 < L) {
            #pragma unroll
            for (int b = 0; b < BH; ++b) out[ob + 2 * (DV * 3) + b * bstr] = acc2[b];
        }
        if (m0 + 3 < L) {
            #pragma unroll
            for (int b = 0; b < BH; ++b) out[ob + 3 * (DV * 3) + b * bstr] = acc3[b];
        }
    }

    // ---- x_v_amn tail ----
    {
        const float* wr = W_amn + (tp * DV + v) * LMAX;
        float acc[BH];
        #pragma unroll
        for (int b = 0; b < BH; ++b) acc[b] = 0.f;

        for (int l = 0; l < L; ++l) {
            const float4* dp = reinterpret_cast<const float4*>(diff_s + (l * 3 + d) * BH);
            float4 q0 = dp[0], q1 = dp[1];
            fma8(acc, __ldg(wr + l), q0, q1);
        }

        const int ob   = amn_base + n * (DV * 3) + b0 * (n_res * DV * 3) + tid;
        const int bamn = n_res * (DV * 3);
        #pragma unroll
        for (int b = 0; b < BH; ++b) out[ob + b * bamn] = acc[b];
    }
}

extern "C" void kernel_launch(void* const* d_in, const int* in_sizes, int n_in,
                              void* d_out, int out_size)
{
    const float* pos_atm = (const float*)d_in[0];
    const float* pos_amn = (const float*)d_in[1];
    const float* W_amn   = (const float*)d_in[2];
    const float* W_atm   = (const float*)d_in[3];
    const int*   seq     = (const int*)d_in[4];

    const int n_res = in_sizes[4];                    // 2048
    const int atoms = in_sizes[0] / (BATCH * 3);      // 15036
    const int amn_base = BATCH * atoms * (DV * 3);    // < 2^31

    float* out = (float*)d_out;

    posmix_scan_kernel<<<1, 256>>>(seq, n_res);
    dim3 grid(n_res, BATCH / BH);
    posmix_kernel<<<grid, TPB>>>(pos_atm, pos_amn, W_amn, W_atm, seq, out,
                                 atoms, n_res, amn_base);
}